// round 16
// baseline (speedup 1.0000x reference)
#include <cuda_runtime.h>

// Two Euler steps of a Gaussian-RBF point flow — single persistent kernel.
// R16: LOAD-BALANCED grid. R15's grid=512 is not a multiple of 148 SMs, so
// placement gives 68 SMs 4 CTAs and 80 SMs 3 -> the heavy SMs set runtime
// (49.2K SMSP-cyc, == measured 25.4us). Fix: grid = 444 = 148*3 (uniform
// 3 CTAs/SM by bid%148 placement), with work split into 1024 fine units per
// phase, strided over CTAs (per-SM imbalance ~1%). Balanced MUFU floor:
// 42.4K cyc ~= 21.4us.
//   Phase A: 1024 units = 256 row-groups (64 rows) x 4 j-quarters.
//   Grid barrier (monotonic counter, div-based target).
//   Phase B: 1024 units = 128 target groups (64 rows) x 8 j-eighths;
//            staging rebuilds shape1 tables from 4-way dp1 partials;
//            8-way parity-flag combine -> output.
// Row-block x2 per lane; FFMA2 packs PAIRS of source points; all exps on
// MUFU (proven floor); safe exponent arg = u*x + v*y + a + cri <= 0.

#define NSRC  2048
#define NTGT  2048
#define NLAND 4096
#define NB    4
#define NCTA  444
#define UA    1024
#define UB    1024
#define TAUF  0.5f
#define LOG2E 1.4426950408889634f

typedef unsigned long long ull;

// Cross-phase scratch (device globals; no allocation).
__device__ float2 g_p1[4][NB * NLAND];   // dp1 partials per j-quarter
__device__ float2 g_p2[8][NB * NTGT];    // dp2 partials per j-eighth
__device__ ull      g_ctr;               // grid barrier, monotonic across calls
__device__ unsigned g_flag[128];         // per-group arrival count, monotonic

__device__ __forceinline__ float ex2f(float x) {
    float y;
    asm("ex2.approx.ftz.f32 %0, %1;" : "=f"(y) : "f"(x));
    return y;
}
__device__ __forceinline__ ull fma2(ull a, ull b, ull c) {
    ull d;
    asm("fma.rn.f32x2 %0, %1, %2, %3;" : "=l"(d) : "l"(a), "l"(b), "l"(c));
    return d;
}
__device__ __forceinline__ ull add2(ull a, ull b) {
    ull d;
    asm("add.rn.f32x2 %0, %1, %2;" : "=l"(d) : "l"(a), "l"(b));
    return d;
}
__device__ __forceinline__ ull pack2(float lo, float hi) {
    ull d;
    asm("mov.b64 %0, {%1, %2};" : "=l"(d) : "f"(lo), "f"(hi));
    return d;
}
__device__ __forceinline__ void unpack2(ull v, float& lo, float& hi) {
    asm("mov.b64 {%0, %1}, %2;" : "=f"(lo), "=f"(hi) : "l"(v));
}

// One row's packed update for a loaded j-pair (all exps on MUFU).
__device__ __forceinline__ void rbf_row(
    ull UVx, ull UVy, ull APa, ull APp, ull PY,
    ull xp, ull yp, ull crip, ull& ax, ull& ay)
{
    ull arg = add2(fma2(UVy, yp, fma2(UVx, xp, APa)), crip);
    float a0, a1;
    unpack2(arg, a0, a1);
    ull wp = pack2(ex2f(a0), ex2f(a1));
    ax = fma2(wp, APp, ax);
    ay = fma2(wp, PY, ay);
}

// ---------------------------------------------------------------------------
__global__ __launch_bounds__(256, 4) void fused_kernel(
    const float2* __restrict__ mom,
    const float2* __restrict__ src,
    const float2* __restrict__ tgt,
    const float*  __restrict__ sig,
    float2*       __restrict__ out)
{
    // No aliasing: sUV [0,4K) | sAP [4K,8K) | sPY [8K,10K) | red [10.25K,18.25K)
    __shared__ __align__(16) char SM[18688];
    float4* sUV = (float4*)(SM);             // [256]
    float4* sAP = (float4*)(SM + 4096);      // [256]
    float2* sPY = (float2*)(SM + 8192);      // [256]
    typedef ull RedRow[256];                 // [warp*32+lane]
    RedRow* red = (RedRow*)(SM + 10496);     // red[4][256] = 8KB

    const int tid  = threadIdx.x;
    const int w    = tid >> 5;
    const int lane = tid & 31;
    const int g    = blockIdx.x;

    const float c2 = -LOG2E / sig[0];
    const float m2 = -2.0f * c2;

    // ======================= Phase A: dp1 partials (4-way) ================
    for (int u = g; u < UA; u += NCTA) {
        const int grp = u >> 2;              // 0..255: 64-row land group
        const int jq  = u & 3;               // j-quarter
        const int i0  = grp * 64;            // global land row base
        const int b   = i0 >> 12;
        const int li  = i0 & (NLAND - 1);

        const float2* __restrict__ srcb = src + b * NSRC;
        const float2* __restrict__ momb = mom + b * NSRC;

        {   // stage 256 pairs; one entry per thread
            const int p = jq * 256 + tid;
            float2 s0 = srcb[2 * p], s1 = srcb[2 * p + 1];
            float2 q0 = momb[2 * p], q1 = momb[2 * p + 1];
            sUV[tid] = make_float4(m2 * s0.x, m2 * s1.x, m2 * s0.y, m2 * s1.y);
            sAP[tid] = make_float4(c2 * (s0.x * s0.x + s0.y * s0.y),
                                   c2 * (s1.x * s1.x + s1.y * s1.y), q0.x, q1.x);
            sPY[tid] = make_float2(q0.y, q1.y);
        }
        __syncthreads();

        const int r0 = li + lane, r1 = r0 + 32;     // same side of 2048
        float2 X0 = (li < NSRC) ? srcb[r0] : tgt[b * NTGT + r0 - NSRC];
        float2 X1 = (li < NSRC) ? srcb[r1] : tgt[b * NTGT + r1 - NSRC];
        const ull xp0 = pack2(X0.x, X0.x), yp0 = pack2(X0.y, X0.y);
        const ull xp1 = pack2(X1.x, X1.x), yp1 = pack2(X1.y, X1.y);
        float c0 = c2 * (X0.x * X0.x + X0.y * X0.y);
        float c1 = c2 * (X1.x * X1.x + X1.y * X1.y);
        const ull cr0 = pack2(c0, c0), cr1 = pack2(c1, c1);

        ull ax0 = 0ull, ay0 = 0ull, ax1 = 0ull, ay1 = 0ull;
        const int qb = w * 32;
        #pragma unroll 8
        for (int t = 0; t < 32; t++) {
            ulonglong2 UV = *(const ulonglong2*)&sUV[qb + t];
            ulonglong2 AP = *(const ulonglong2*)&sAP[qb + t];
            ull PY = *(const ull*)&sPY[qb + t];
            rbf_row(UV.x, UV.y, AP.x, AP.y, PY, xp0, yp0, cr0, ax0, ay0);
            rbf_row(UV.x, UV.y, AP.x, AP.y, PY, xp1, yp1, cr1, ax1, ay1);
        }
        __syncthreads();                     // prior w0 red-reads are long done
        red[0][w * 32 + lane] = ax0;
        red[1][w * 32 + lane] = ay0;
        red[2][w * 32 + lane] = ax1;
        red[3][w * 32 + lane] = ay1;
        __syncthreads();

        if (w == 0) {
            ull s0 = red[0][lane], s1 = red[1][lane];
            ull s2 = red[2][lane], s3 = red[3][lane];
            #pragma unroll
            for (int ww = 1; ww < 8; ww++) {
                s0 = add2(s0, red[0][ww * 32 + lane]);
                s1 = add2(s1, red[1][ww * 32 + lane]);
                s2 = add2(s2, red[2][ww * 32 + lane]);
                s3 = add2(s3, red[3][ww * 32 + lane]);
            }
            float e0, e1, f0, f1;
            unpack2(s0, e0, e1); unpack2(s1, f0, f1);
            g_p1[jq][i0 + lane] = make_float2(e0 + e1, f0 + f1);
            unpack2(s2, e0, e1); unpack2(s3, f0, f1);
            g_p1[jq][i0 + 32 + lane] = make_float2(e0 + e1, f0 + f1);
        }
        __syncthreads();                     // red reads done before next unit
    }

    // ======================= Grid barrier =======================
    __threadfence();
    __syncthreads();
    if (tid == 0) {
        ull old = atomicAdd(&g_ctr, 1ull);
        ull target = (old / (ull)NCTA) * (ull)NCTA + (ull)NCTA;
        while (*(volatile ull*)&g_ctr < target) __nanosleep(32);
        __threadfence();
    }
    __syncthreads();

    // ======================= Phase B: dp2 (8-way) + output ================
    for (int u = g; u < UB; u += NCTA) {
        const int grp = u >> 3;              // 0..127: 64-row target group
        const int je  = u & 7;               // j-eighth
        const int t0  = grp * 64;            // global target row base
        const int b   = t0 >> 11;

        // Stage 128 pairs, rebuilding shape1 pack from 4-way dp1 partials.
        if (tid < 128) {
            const int p = je * 128 + tid;    // pair within batch
            const int j0 = 2 * p, j1 = 2 * p + 1;
            const int l0 = b * NLAND + j0, l1 = b * NLAND + j1;
            float2 d0 = g_p1[0][l0], d1 = g_p1[1][l0];
            float2 d2 = g_p1[2][l0], d3 = g_p1[3][l0];
            float2 e0 = g_p1[0][l1], e1 = g_p1[1][l1];
            float2 e2 = g_p1[2][l1], e3 = g_p1[3][l1];
            float2 s0 = src[b * NSRC + j0], s1 = src[b * NSRC + j1];
            float2 q0 = mom[b * NSRC + j0], q1 = mom[b * NSRC + j1];
            float s0x = fmaf(TAUF, (d0.x + d1.x) + (d2.x + d3.x), s0.x);
            float s0y = fmaf(TAUF, (d0.y + d1.y) + (d2.y + d3.y), s0.y);
            float s1x = fmaf(TAUF, (e0.x + e1.x) + (e2.x + e3.x), s1.x);
            float s1y = fmaf(TAUF, (e0.y + e1.y) + (e2.y + e3.y), s1.y);
            sUV[tid] = make_float4(m2 * s0x, m2 * s1x, m2 * s0y, m2 * s1y);
            sAP[tid] = make_float4(c2 * (s0x * s0x + s0y * s0y),
                                   c2 * (s1x * s1x + s1y * s1y), q0.x, q1.x);
            sPY[tid] = make_float2(q0.y, q1.y);
        }
        __syncthreads();

        // This lane's two target rows, advected to shape1 (4-way partials).
        const int ta = t0 + lane, tb2 = ta + 32;
        const int la = b * NLAND + NSRC + (ta & (NTGT - 1));
        const int lb = b * NLAND + NSRC + (tb2 & (NTGT - 1));
        float2 Ta = tgt[ta], Tb = tgt[tb2];
        float2 da0 = g_p1[0][la], da1 = g_p1[1][la];
        float2 da2 = g_p1[2][la], da3 = g_p1[3][la];
        float2 db0 = g_p1[0][lb], db1 = g_p1[1][lb];
        float2 db2 = g_p1[2][lb], db3 = g_p1[3][lb];
        float2 X0 = make_float2(
            fmaf(TAUF, (da0.x + da1.x) + (da2.x + da3.x), Ta.x),
            fmaf(TAUF, (da0.y + da1.y) + (da2.y + da3.y), Ta.y));
        float2 X1 = make_float2(
            fmaf(TAUF, (db0.x + db1.x) + (db2.x + db3.x), Tb.x),
            fmaf(TAUF, (db0.y + db1.y) + (db2.y + db3.y), Tb.y));
        const ull xp0 = pack2(X0.x, X0.x), yp0 = pack2(X0.y, X0.y);
        const ull xp1 = pack2(X1.x, X1.x), yp1 = pack2(X1.y, X1.y);
        float c0 = c2 * (X0.x * X0.x + X0.y * X0.y);
        float c1 = c2 * (X1.x * X1.x + X1.y * X1.y);
        const ull cr0 = pack2(c0, c0), cr1 = pack2(c1, c1);

        ull ax0 = 0ull, ay0 = 0ull, ax1 = 0ull, ay1 = 0ull;
        const int qb = w * 16;
        #pragma unroll 8
        for (int t = 0; t < 16; t++) {
            ulonglong2 UV = *(const ulonglong2*)&sUV[qb + t];
            ulonglong2 AP = *(const ulonglong2*)&sAP[qb + t];
            ull PY = *(const ull*)&sPY[qb + t];
            rbf_row(UV.x, UV.y, AP.x, AP.y, PY, xp0, yp0, cr0, ax0, ay0);
            rbf_row(UV.x, UV.y, AP.x, AP.y, PY, xp1, yp1, cr1, ax1, ay1);
        }
        __syncthreads();
        red[0][w * 32 + lane] = ax0;
        red[1][w * 32 + lane] = ay0;
        red[2][w * 32 + lane] = ax1;
        red[3][w * 32 + lane] = ay1;
        __syncthreads();

        if (w == 0) {
            ull s0 = red[0][lane], s1 = red[1][lane];
            ull s2 = red[2][lane], s3 = red[3][lane];
            #pragma unroll
            for (int ww = 1; ww < 8; ww++) {
                s0 = add2(s0, red[0][ww * 32 + lane]);
                s1 = add2(s1, red[1][ww * 32 + lane]);
                s2 = add2(s2, red[2][ww * 32 + lane]);
                s3 = add2(s3, red[3][ww * 32 + lane]);
            }
            float e0, e1, f0, f1;
            unpack2(s0, e0, e1); unpack2(s1, f0, f1);
            g_p2[je][ta] = make_float2(e0 + e1, f0 + f1);
            unpack2(s2, e0, e1); unpack2(s3, f0, f1);
            g_p2[je][tb2] = make_float2(e0 + e1, f0 + f1);

            __threadfence();                 // release partials
            __syncwarp();
            unsigned old = 0;
            if (lane == 0) old = atomicAdd(&g_flag[grp], 1u);
            old = __shfl_sync(0xffffffffu, old, 0);
            if ((old & 7u) == 7u) {          // 8th arrival: combine + writeout
                __threadfence();             // acquire peer partials
                float sxa = X0.x, sya = X0.y, sxb = X1.x, syb = X1.y;
                float dxa = 0.f, dya = 0.f, dxb = 0.f, dyb = 0.f;
                #pragma unroll
                for (int k = 0; k < 8; k++) {
                    float2 pa = __ldcg(&g_p2[k][ta]);
                    float2 pb = __ldcg(&g_p2[k][tb2]);
                    dxa += pa.x; dya += pa.y;
                    dxb += pb.x; dyb += pb.y;
                }
                out[ta]  = make_float2(fmaf(TAUF, dxa, sxa), fmaf(TAUF, dya, sya));
                out[tb2] = make_float2(fmaf(TAUF, dxb, sxb), fmaf(TAUF, dyb, syb));
            }
        }
        __syncthreads();                     // red reads done before next unit
    }
}

// ---------------------------------------------------------------------------
extern "C" void kernel_launch(void* const* d_in, const int* in_sizes, int n_in,
                              void* d_out, int out_size)
{
    const float2* mom = (const float2*)d_in[0];
    const float2* src = (const float2*)d_in[1];
    const float2* tgt = (const float2*)d_in[2];
    const float*  sig = (const float*)d_in[3];
    float2* out = (float2*)d_out;

    fused_kernel<<<NCTA, 256>>>(mom, src, tgt, sig, out);
}

// round 17
// speedup vs baseline: 1.1070x; 1.1070x over previous
#include <cuda_runtime.h>

// Two Euler steps of a Gaussian-RBF point flow — single persistent kernel.
// R17: load balance WITHOUT extra staging events (R16's mistake). CTAs are
// reshaped to 128 threads (4 warps) and the grid to 1024: placement gives
// 136 SMs x 7 CTAs + 12 x 6 (1.2% imbalance vs R15's 16% at grid=512).
// Each CTA stages its j-table ONCE per phase (R15 flow at half scale).
// Heavy-SM MUFU cycles: 7/SMSP x 384 exps x rt16 = 43.0K (~21.7us) vs
// R15's measured 49.2K (~24.8us).
//   Phase A: 1024 CTAs = 256 row-groups (64 rows) x 4 j-quarters.
//   Grid barrier (monotonic counter; all 1024 CTAs wave-1 resident:
//   64regs x 128thr x 8 = 64K regs/SM, ~13KB smem x 8 << 228KB).
//   Phase B: 1024 CTAs = 128 target groups x 8 j-eighths; staging rebuilds
//   shape1 tables from 4-way dp1 partials; 8-way parity combine -> output.
// Row-block x2 per lane; FFMA2 packs PAIRS of source points; all exps on
// MUFU (proven floor); safe exponent arg = u*x + v*y + a + cri <= 0.

#define NSRC  2048
#define NTGT  2048
#define NLAND 4096
#define NB    4
#define NCTA  1024
#define TAUF  0.5f
#define LOG2E 1.4426950408889634f

typedef unsigned long long ull;

// Cross-phase scratch (device globals; no allocation).
__device__ float2 g_p1[4][NB * NLAND];   // dp1 partials per j-quarter
__device__ float2 g_p2[8][NB * NTGT];    // dp2 partials per j-eighth
__device__ ull      g_ctr;               // grid barrier, monotonic across calls
__device__ unsigned g_flag[128];         // per-group arrival count, monotonic

__device__ __forceinline__ float ex2f(float x) {
    float y;
    asm("ex2.approx.ftz.f32 %0, %1;" : "=f"(y) : "f"(x));
    return y;
}
__device__ __forceinline__ ull fma2(ull a, ull b, ull c) {
    ull d;
    asm("fma.rn.f32x2 %0, %1, %2, %3;" : "=l"(d) : "l"(a), "l"(b), "l"(c));
    return d;
}
__device__ __forceinline__ ull add2(ull a, ull b) {
    ull d;
    asm("add.rn.f32x2 %0, %1, %2;" : "=l"(d) : "l"(a), "l"(b));
    return d;
}
__device__ __forceinline__ ull pack2(float lo, float hi) {
    ull d;
    asm("mov.b64 %0, {%1, %2};" : "=l"(d) : "f"(lo), "f"(hi));
    return d;
}
__device__ __forceinline__ void unpack2(ull v, float& lo, float& hi) {
    asm("mov.b64 {%0, %1}, %2;" : "=f"(lo), "=f"(hi) : "l"(v));
}

// One row's packed update for a loaded j-pair (all exps on MUFU).
__device__ __forceinline__ void rbf_row(
    ull UVx, ull UVy, ull APa, ull APp, ull PY,
    ull xp, ull yp, ull crip, ull& ax, ull& ay)
{
    ull arg = add2(fma2(UVy, yp, fma2(UVx, xp, APa)), crip);
    float a0, a1;
    unpack2(arg, a0, a1);
    ull wp = pack2(ex2f(a0), ex2f(a1));
    ax = fma2(wp, APp, ax);
    ay = fma2(wp, PY, ay);
}

// ---------------------------------------------------------------------------
__global__ __launch_bounds__(128, 8) void fused_kernel(
    const float2* __restrict__ mom,
    const float2* __restrict__ src,
    const float2* __restrict__ tgt,
    const float*  __restrict__ sig,
    float2*       __restrict__ out)
{
    // sUV [0,4K) | sAP [4K,8K) | sPY [8K,10K) | red [10.25K,14.25K)
    __shared__ __align__(16) char SM[14592];
    float4* sUV = (float4*)(SM);             // [256]
    float4* sAP = (float4*)(SM + 4096);      // [256]
    float2* sPY = (float2*)(SM + 8192);      // [256]
    typedef ull RedRow[128];                 // [warp*32+lane]
    RedRow* red = (RedRow*)(SM + 10496);     // red[4][128] = 4KB

    const int tid  = threadIdx.x;
    const int w    = tid >> 5;               // 0..3
    const int lane = tid & 31;
    const int g    = blockIdx.x;

    const float c2 = -LOG2E / sig[0];
    const float m2 = -2.0f * c2;

    // ======================= Phase A: dp1 partials (4-way) ================
    {
        const int grp = g >> 2;              // 0..255: 64-row land group
        const int jq  = g & 3;               // j-quarter
        const int i0  = grp * 64;            // global land row base
        const int b   = i0 >> 12;
        const int li  = i0 & (NLAND - 1);

        const float2* __restrict__ srcb = src + b * NSRC;
        const float2* __restrict__ momb = mom + b * NSRC;

        // Stage this CTA's 256 j-pairs ONCE (2 entries/thread).
        for (int q = tid; q < 256; q += 128) {
            const int p = jq * 256 + q;
            float2 s0 = srcb[2 * p], s1 = srcb[2 * p + 1];
            float2 q0 = momb[2 * p], q1 = momb[2 * p + 1];
            sUV[q] = make_float4(m2 * s0.x, m2 * s1.x, m2 * s0.y, m2 * s1.y);
            sAP[q] = make_float4(c2 * (s0.x * s0.x + s0.y * s0.y),
                                 c2 * (s1.x * s1.x + s1.y * s1.y), q0.x, q1.x);
            sPY[q] = make_float2(q0.y, q1.y);
        }
        __syncthreads();

        const int r0 = li + lane, r1 = r0 + 32;     // same side of 2048
        float2 X0 = (li < NSRC) ? srcb[r0] : tgt[b * NTGT + r0 - NSRC];
        float2 X1 = (li < NSRC) ? srcb[r1] : tgt[b * NTGT + r1 - NSRC];
        const ull xp0 = pack2(X0.x, X0.x), yp0 = pack2(X0.y, X0.y);
        const ull xp1 = pack2(X1.x, X1.x), yp1 = pack2(X1.y, X1.y);
        float c0 = c2 * (X0.x * X0.x + X0.y * X0.y);
        float c1 = c2 * (X1.x * X1.x + X1.y * X1.y);
        const ull cr0 = pack2(c0, c0), cr1 = pack2(c1, c1);

        ull ax0 = 0ull, ay0 = 0ull, ax1 = 0ull, ay1 = 0ull;
        const int qb = w * 64;               // 4 warps x 64 steps
        #pragma unroll 8
        for (int t = 0; t < 64; t++) {
            ulonglong2 UV = *(const ulonglong2*)&sUV[qb + t];
            ulonglong2 AP = *(const ulonglong2*)&sAP[qb + t];
            ull PY = *(const ull*)&sPY[qb + t];
            rbf_row(UV.x, UV.y, AP.x, AP.y, PY, xp0, yp0, cr0, ax0, ay0);
            rbf_row(UV.x, UV.y, AP.x, AP.y, PY, xp1, yp1, cr1, ax1, ay1);
        }
        __syncthreads();
        red[0][w * 32 + lane] = ax0;
        red[1][w * 32 + lane] = ay0;
        red[2][w * 32 + lane] = ax1;
        red[3][w * 32 + lane] = ay1;
        __syncthreads();

        if (w == 0) {
            ull s0 = red[0][lane], s1 = red[1][lane];
            ull s2 = red[2][lane], s3 = red[3][lane];
            #pragma unroll
            for (int ww = 1; ww < 4; ww++) {
                s0 = add2(s0, red[0][ww * 32 + lane]);
                s1 = add2(s1, red[1][ww * 32 + lane]);
                s2 = add2(s2, red[2][ww * 32 + lane]);
                s3 = add2(s3, red[3][ww * 32 + lane]);
            }
            float e0, e1, f0, f1;
            unpack2(s0, e0, e1); unpack2(s1, f0, f1);
            g_p1[jq][i0 + lane] = make_float2(e0 + e1, f0 + f1);
            unpack2(s2, e0, e1); unpack2(s3, f0, f1);
            g_p1[jq][i0 + 32 + lane] = make_float2(e0 + e1, f0 + f1);
        }
    }

    // ======================= Grid barrier =======================
    __threadfence();
    __syncthreads();
    if (tid == 0) {
        ull old = atomicAdd(&g_ctr, 1ull);
        ull target = (old & ~(ull)(NCTA - 1)) + (ull)NCTA;
        while (*(volatile ull*)&g_ctr < target) __nanosleep(32);
        __threadfence();
    }
    __syncthreads();

    // ======================= Phase B: dp2 (8-way) + output ================
    {
        const int grp = g >> 3;              // 0..127: 64-row target group
        const int je  = g & 7;               // j-eighth
        const int t0  = grp * 64;            // global target row base
        const int b   = t0 >> 11;

        // Stage this CTA's 128 j-pairs (1 entry/thread), rebuilding the
        // shape1 pack from 4-way dp1 partials.
        {
            const int p = je * 128 + tid;    // pair within batch
            const int j0 = 2 * p, j1 = 2 * p + 1;
            const int l0 = b * NLAND + j0, l1 = b * NLAND + j1;
            float2 d0 = g_p1[0][l0], d1 = g_p1[1][l0];
            float2 d2 = g_p1[2][l0], d3 = g_p1[3][l0];
            float2 e0 = g_p1[0][l1], e1 = g_p1[1][l1];
            float2 e2 = g_p1[2][l1], e3 = g_p1[3][l1];
            float2 s0 = src[b * NSRC + j0], s1 = src[b * NSRC + j1];
            float2 q0 = mom[b * NSRC + j0], q1 = mom[b * NSRC + j1];
            float s0x = fmaf(TAUF, (d0.x + d1.x) + (d2.x + d3.x), s0.x);
            float s0y = fmaf(TAUF, (d0.y + d1.y) + (d2.y + d3.y), s0.y);
            float s1x = fmaf(TAUF, (e0.x + e1.x) + (e2.x + e3.x), s1.x);
            float s1y = fmaf(TAUF, (e0.y + e1.y) + (e2.y + e3.y), s1.y);
            sUV[tid] = make_float4(m2 * s0x, m2 * s1x, m2 * s0y, m2 * s1y);
            sAP[tid] = make_float4(c2 * (s0x * s0x + s0y * s0y),
                                   c2 * (s1x * s1x + s1y * s1y), q0.x, q1.x);
            sPY[tid] = make_float2(q0.y, q1.y);
        }
        __syncthreads();

        // This lane's two target rows, advected to shape1 (4-way partials).
        const int ta = t0 + lane, tb2 = ta + 32;
        const int la = b * NLAND + NSRC + (ta & (NTGT - 1));
        const int lb = b * NLAND + NSRC + (tb2 & (NTGT - 1));
        float2 Ta = tgt[ta], Tb = tgt[tb2];
        float2 da0 = g_p1[0][la], da1 = g_p1[1][la];
        float2 da2 = g_p1[2][la], da3 = g_p1[3][la];
        float2 db0 = g_p1[0][lb], db1 = g_p1[1][lb];
        float2 db2 = g_p1[2][lb], db3 = g_p1[3][lb];
        float2 X0 = make_float2(
            fmaf(TAUF, (da0.x + da1.x) + (da2.x + da3.x), Ta.x),
            fmaf(TAUF, (da0.y + da1.y) + (da2.y + da3.y), Ta.y));
        float2 X1 = make_float2(
            fmaf(TAUF, (db0.x + db1.x) + (db2.x + db3.x), Tb.x),
            fmaf(TAUF, (db0.y + db1.y) + (db2.y + db3.y), Tb.y));
        const ull xp0 = pack2(X0.x, X0.x), yp0 = pack2(X0.y, X0.y);
        const ull xp1 = pack2(X1.x, X1.x), yp1 = pack2(X1.y, X1.y);
        float c0 = c2 * (X0.x * X0.x + X0.y * X0.y);
        float c1 = c2 * (X1.x * X1.x + X1.y * X1.y);
        const ull cr0 = pack2(c0, c0), cr1 = pack2(c1, c1);

        ull ax0 = 0ull, ay0 = 0ull, ax1 = 0ull, ay1 = 0ull;
        const int qb = w * 32;               // 4 warps x 32 steps
        #pragma unroll 8
        for (int t = 0; t < 32; t++) {
            ulonglong2 UV = *(const ulonglong2*)&sUV[qb + t];
            ulonglong2 AP = *(const ulonglong2*)&sAP[qb + t];
            ull PY = *(const ull*)&sPY[qb + t];
            rbf_row(UV.x, UV.y, AP.x, AP.y, PY, xp0, yp0, cr0, ax0, ay0);
            rbf_row(UV.x, UV.y, AP.x, AP.y, PY, xp1, yp1, cr1, ax1, ay1);
        }
        __syncthreads();
        red[0][w * 32 + lane] = ax0;
        red[1][w * 32 + lane] = ay0;
        red[2][w * 32 + lane] = ax1;
        red[3][w * 32 + lane] = ay1;
        __syncthreads();

        if (w == 0) {
            ull s0 = red[0][lane], s1 = red[1][lane];
            ull s2 = red[2][lane], s3 = red[3][lane];
            #pragma unroll
            for (int ww = 1; ww < 4; ww++) {
                s0 = add2(s0, red[0][ww * 32 + lane]);
                s1 = add2(s1, red[1][ww * 32 + lane]);
                s2 = add2(s2, red[2][ww * 32 + lane]);
                s3 = add2(s3, red[3][ww * 32 + lane]);
            }
            float e0, e1, f0, f1;
            unpack2(s0, e0, e1); unpack2(s1, f0, f1);
            g_p2[je][ta] = make_float2(e0 + e1, f0 + f1);
            unpack2(s2, e0, e1); unpack2(s3, f0, f1);
            g_p2[je][tb2] = make_float2(e0 + e1, f0 + f1);

            __threadfence();                 // release partials
            __syncwarp();
            unsigned old = 0;
            if (lane == 0) old = atomicAdd(&g_flag[grp], 1u);
            old = __shfl_sync(0xffffffffu, old, 0);
            if ((old & 7u) == 7u) {          // 8th arrival: combine + writeout
                __threadfence();             // acquire peer partials
                float dxa = 0.f, dya = 0.f, dxb = 0.f, dyb = 0.f;
                #pragma unroll
                for (int k = 0; k < 8; k++) {
                    float2 pa = __ldcg(&g_p2[k][ta]);
                    float2 pb = __ldcg(&g_p2[k][tb2]);
                    dxa += pa.x; dya += pa.y;
                    dxb += pb.x; dyb += pb.y;
                }
                out[ta]  = make_float2(fmaf(TAUF, dxa, X0.x),
                                       fmaf(TAUF, dya, X0.y));
                out[tb2] = make_float2(fmaf(TAUF, dxb, X1.x),
                                       fmaf(TAUF, dyb, X1.y));
            }
        }
    }
}

// ---------------------------------------------------------------------------
extern "C" void kernel_launch(void* const* d_in, const int* in_sizes, int n_in,
                              void* d_out, int out_size)
{
    const float2* mom = (const float2*)d_in[0];
    const float2* src = (const float2*)d_in[1];
    const float2* tgt = (const float2*)d_in[2];
    const float*  sig = (const float*)d_in[3];
    float2* out = (float2*)d_out;

    fused_kernel<<<NCTA, 128>>>(mom, src, tgt, sig, out);
}